// round 7
// baseline (speedup 1.0000x reference)
#include <cuda_runtime.h>
#include <cuda_bf16.h>
#include <cuda_fp8.h>
#include <cstdint>

// ============================================================================
// Problem constants — inputs and output are FLOAT32 buffers (bf16 values
// materialized as f32 by the harness; output compared as f32 of bf16 values)
// ============================================================================
static constexpr int K_DIM = 2048;
static constexpr int N_DIM = 2048;
static constexpr int M_MAX = 8192;

// amax partials layout
static constexpr int XBLK = 1536;   // partial-max blocks for x
static constexpr int WBLK = 768;    // partial-max blocks for w
static constexpr int QXB  = 2048;   // quant blocks for x
static constexpr int QWB  = 1024;   // quant blocks for w

// fp8 scratch + scalars (device globals — no allocation allowed)
__device__ __align__(128) unsigned char g_x_fp8[(size_t)M_MAX * K_DIM];  // 16 MB
__device__ __align__(128) unsigned char g_w_fp8[(size_t)N_DIM * K_DIM]; //  4 MB
__device__ float g_part[XBLK + WBLK];  // per-block partial maxes (pure writes)
__device__ float g_scale[2];           // per-tensor scale
__device__ float g_scale_comb;         // sx*sw for epilogue

__device__ __forceinline__ uint32_t smem_to_u32(const void* smem_ptr) {
    uint32_t addr;
    asm("{ .reg .u64 tmp; cvta.to.shared.u64 tmp, %1; cvt.u32.u64 %0, tmp; }"
        : "=r"(addr) : "l"(smem_ptr));
    return addr;
}

#define CP_ASYNC16(dst, src) \
    asm volatile("cp.async.cg.shared.global [%0], [%1], 16;" :: "r"(dst), "l"(src) : "memory")
#define CP_ASYNC_COMMIT() asm volatile("cp.async.commit_group;" ::: "memory")
#define CP_ASYNC_WAIT3()  asm volatile("cp.async.wait_group 3;" ::: "memory")

#define LDMATRIX_X4(r0, r1, r2, r3, addr) \
    asm volatile("ldmatrix.sync.aligned.m8n8.x4.shared.b16 {%0,%1,%2,%3}, [%4];" \
                 : "=r"(r0), "=r"(r1), "=r"(r2), "=r"(r3) : "r"(addr))

#define MMA_E4M3(c0, c1, c2, c3, a0, a1, a2, a3, b0, b1) \
    asm volatile("mma.sync.aligned.m16n8k32.row.col.f32.e4m3.e4m3.f32 " \
                 "{%0,%1,%2,%3}, {%4,%5,%6,%7}, {%8,%9}, {%0,%1,%2,%3};" \
                 : "+f"(c0), "+f"(c1), "+f"(c2), "+f"(c3) \
                 : "r"(a0), "r"(a1), "r"(a2), "r"(a3), "r"(b0), "r"(b1))

// ============================================================================
// Kernel 1: fused amax over both tensors -> per-block partials (no reset/atomic)
// ============================================================================
__device__ __forceinline__ float block_reduce_max(float m) {
    #pragma unroll
    for (int o = 16; o > 0; o >>= 1)
        m = fmaxf(m, __shfl_xor_sync(0xFFFFFFFFu, m, o));
    __shared__ float smax[8];
    int wid = threadIdx.x >> 5, lid = threadIdx.x & 31;
    if (lid == 0) smax[wid] = m;
    __syncthreads();
    if (wid == 0) {
        m = (lid < (int)(blockDim.x >> 5)) ? smax[lid] : 0.0f;
        #pragma unroll
        for (int o = 4; o > 0; o >>= 1)
            m = fmaxf(m, __shfl_xor_sync(0xFFFFFFFFu, m, o));
    }
    return m;
}

__global__ void amax_both_kernel(const float* __restrict__ x, size_t nx4,
                                 const float* __restrict__ w, size_t nw4) {
    bool is_x = (blockIdx.x < XBLK);
    const float4* p = reinterpret_cast<const float4*>(is_x ? x : w);
    size_t n4   = is_x ? nx4 : nw4;
    int    bid  = is_x ? blockIdx.x : (blockIdx.x - XBLK);
    int    nblk = is_x ? XBLK : WBLK;

    float m = 0.0f;
    size_t i = (size_t)bid * blockDim.x + threadIdx.x;
    size_t stride = (size_t)nblk * blockDim.x;
    for (; i < n4; i += stride) {
        float4 v = p[i];
        m = fmaxf(m, fmaxf(fmaxf(fabsf(v.x), fabsf(v.y)),
                           fmaxf(fabsf(v.z), fabsf(v.w))));
    }
    m = block_reduce_max(m);
    if (threadIdx.x == 0) g_part[blockIdx.x] = m;
}

// ============================================================================
// Kernel 2: reduce partials -> scales (pure function of g_part; no state)
// ============================================================================
__global__ void scales_kernel() {
    int tid = threadIdx.x;   // 256 threads
    float mx = 0.0f, mw = 0.0f;
    for (int i = tid; i < XBLK; i += 256) mx = fmaxf(mx, g_part[i]);
    for (int i = XBLK + tid; i < XBLK + WBLK; i += 256) mw = fmaxf(mw, g_part[i]);
    // reduce both through shuffles + smem
    #pragma unroll
    for (int o = 16; o > 0; o >>= 1) {
        mx = fmaxf(mx, __shfl_xor_sync(0xFFFFFFFFu, mx, o));
        mw = fmaxf(mw, __shfl_xor_sync(0xFFFFFFFFu, mw, o));
    }
    __shared__ float sx8[8], sw8[8];
    int wid = tid >> 5, lid = tid & 31;
    if (lid == 0) { sx8[wid] = mx; sw8[wid] = mw; }
    __syncthreads();
    if (tid == 0) {
        float ax = 0.0f, aw = 0.0f;
        #pragma unroll
        for (int i = 0; i < 8; i++) {
            ax = fmaxf(ax, sx8[i]);
            aw = fmaxf(aw, sw8[i]);
        }
        float sxv = fmaxf(__fdiv_rn(ax, 448.0f), 1e-12f);
        float swv = fmaxf(__fdiv_rn(aw, 448.0f), 1e-12f);
        g_scale[0] = sxv;
        g_scale[1] = swv;
        g_scale_comb = sxv * swv;
    }
}

// ============================================================================
// Kernel 3: fused quantize f32 -> e4m3 for both tensors (RNE satfinite)
// ============================================================================
__global__ void quant_both_kernel(const float* __restrict__ x, unsigned char* __restrict__ xq, size_t nx8,
                                  const float* __restrict__ w, unsigned char* __restrict__ wq, size_t nw8) {
    bool is_x = (blockIdx.x < QXB);
    const float4* p = reinterpret_cast<const float4*>(is_x ? x : w);
    uint2* q  = reinterpret_cast<uint2*>(is_x ? xq : wq);
    size_t n8 = is_x ? nx8 : nw8;
    int bid   = is_x ? blockIdx.x : (blockIdx.x - QXB);
    int nblk  = is_x ? QXB : QWB;
    float s   = g_scale[is_x ? 0 : 1];

    size_t i = (size_t)bid * blockDim.x + threadIdx.x;
    size_t stride = (size_t)nblk * blockDim.x;
    for (; i < n8; i += stride) {
        float4 v0 = p[2 * i];
        float4 v1 = p[2 * i + 1];
        float2 f0 = make_float2(__fdiv_rn(v0.x, s), __fdiv_rn(v0.y, s));
        float2 f1 = make_float2(__fdiv_rn(v0.z, s), __fdiv_rn(v0.w, s));
        float2 f2 = make_float2(__fdiv_rn(v1.x, s), __fdiv_rn(v1.y, s));
        float2 f3 = make_float2(__fdiv_rn(v1.z, s), __fdiv_rn(v1.w, s));
        uint32_t b0 = __nv_cvt_float2_to_fp8x2(f0, __NV_SATFINITE, __NV_E4M3);
        uint32_t b1 = __nv_cvt_float2_to_fp8x2(f1, __NV_SATFINITE, __NV_E4M3);
        uint32_t b2 = __nv_cvt_float2_to_fp8x2(f2, __NV_SATFINITE, __NV_E4M3);
        uint32_t b3 = __nv_cvt_float2_to_fp8x2(f3, __NV_SATFINITE, __NV_E4M3);
        uint2 r;
        r.x = (b0 & 0xFFFFu) | (b1 << 16);
        r.y = (b2 & 0xFFFFu) | (b3 << 16);
        q[i] = r;
    }
}

// ============================================================================
// Kernel 4: FP8 GEMM via mma.sync.m16n8k32 e4m3
//   out[m,n] = f32(bf16(sc * sum_k A[m,k]*B[n,k]))
//   CTA 128x128, BK=64, 5-stage cp.async pipeline, 256 threads, 2 CTA/SM.
// ============================================================================
static constexpr int BM = 128, BN = 128, BK = 64;
static constexpr int STAGES = 5;
static constexpr int PITCH = 80;                    // bytes/row: conflict-free
static constexpr int TILE_A = BM * PITCH;           // 10240 bytes
static constexpr int STAGE_B = 2 * TILE_A;          // 20480 bytes per stage
static constexpr int GEMM_SMEM = STAGES * STAGE_B;  // 102400 bytes
static constexpr int KITERS = K_DIM / BK;           // 32

__device__ __forceinline__ void load_stage(
    const uint8_t* __restrict__ Aq, const uint8_t* __restrict__ Bq,
    uint32_t sbase, int ki, int m0, int n0, int tid)
{
    uint32_t sdst = sbase + (ki % STAGES) * STAGE_B;
    int kb = ki * BK;
    #pragma unroll
    for (int p = 0; p < 4; p++) {
        int id  = p * 256 + tid;
        int rid = id & 511;
        int row = rid >> 2;
        int ch  = rid & 3;
        const uint8_t* src;
        uint32_t dst;
        if (p < 2) {  // A chunks
            src = Aq + (size_t)(m0 + row) * K_DIM + kb + ch * 16;
            dst = sdst + row * PITCH + ch * 16;
        } else {      // B chunks
            src = Bq + (size_t)(n0 + row) * K_DIM + kb + ch * 16;
            dst = sdst + TILE_A + row * PITCH + ch * 16;
        }
        CP_ASYNC16(dst, src);
    }
}

__global__ void __launch_bounds__(256, 2) gemm_kernel(
    const uint8_t* __restrict__ Aq, const uint8_t* __restrict__ Bq,
    float* __restrict__ out)
{
    extern __shared__ char smem[];
    uint32_t sbase = smem_to_u32(smem);
    int tid  = threadIdx.x;
    int lane = tid & 31;
    int wid  = tid >> 5;
    int warp_m = wid & 1;   // 0..1
    int warp_n = wid >> 1;  // 0..3
    int m0 = blockIdx.x * BM;
    int n0 = blockIdx.y * BN;

    float c[4][4][4];
    #pragma unroll
    for (int mf = 0; mf < 4; mf++)
        #pragma unroll
        for (int nf = 0; nf < 4; nf++)
            #pragma unroll
            for (int e = 0; e < 4; e++) c[mf][nf][e] = 0.0f;

    #pragma unroll
    for (int ki = 0; ki < STAGES - 1; ki++) {
        load_stage(Aq, Bq, sbase, ki, m0, n0, tid);
        CP_ASYNC_COMMIT();
    }

    int frow = lane & 15;   // row within 16-row fragment
    int fch  = lane >> 4;   // 16-byte chunk select

    for (int ki = 0; ki < KITERS; ki++) {
        CP_ASYNC_WAIT3();
        __syncthreads();

        if (ki + STAGES - 1 < KITERS)
            load_stage(Aq, Bq, sbase, ki + STAGES - 1, m0, n0, tid);
        CP_ASYNC_COMMIT();

        uint32_t sA = sbase + (ki % STAGES) * STAGE_B;
        uint32_t sB = sA + TILE_A;

        #pragma unroll
        for (int ks = 0; ks < 2; ks++) {          // kk = ks*32
            int cbase = (ks << 1) + fch;          // 16B-chunk index 0..3
            uint32_t aAddr = sA + (warp_m * 64 + frow) * PITCH + cbase * 16;
            uint32_t bAddr = sB + (warp_n * 32 + frow) * PITCH + cbase * 16;

            uint32_t a[4][4];
            #pragma unroll
            for (int mf = 0; mf < 4; mf++)
                LDMATRIX_X4(a[mf][0], a[mf][1], a[mf][2], a[mf][3],
                            aAddr + mf * 16 * PITCH);

            uint32_t b[4][2];
            #pragma unroll
            for (int nfp = 0; nfp < 2; nfp++) {
                uint32_t r0, r1, r2, r3;
                LDMATRIX_X4(r0, r1, r2, r3, bAddr + nfp * 16 * PITCH);
                b[2 * nfp][0]     = r0;  b[2 * nfp][1]     = r2;  // n rows 0-7
                b[2 * nfp + 1][0] = r1;  b[2 * nfp + 1][1] = r3;  // n rows 8-15
            }

            #pragma unroll
            for (int mf = 0; mf < 4; mf++)
                #pragma unroll
                for (int nf = 0; nf < 4; nf++)
                    MMA_E4M3(c[mf][nf][0], c[mf][nf][1], c[mf][nf][2], c[mf][nf][3],
                             a[mf][0], a[mf][1], a[mf][2], a[mf][3],
                             b[nf][0], b[nf][1]);
        }
        __syncthreads();
    }

    // epilogue: scale, round to bf16 (reference casts to bf16), store as f32
    float sc = g_scale_comb;
    int r  = lane >> 2;
    int cq = (lane & 3) * 2;
    #pragma unroll
    for (int mf = 0; mf < 4; mf++) {
        #pragma unroll
        for (int nf = 0; nf < 4; nf++) {
            int gm = m0 + warp_m * 64 + mf * 16 + r;
            int gn = n0 + warp_n * 32 + nf * 8 + cq;
            float2 e0, e1;
            e0.x = __bfloat162float(__float2bfloat16_rn(c[mf][nf][0] * sc));
            e0.y = __bfloat162float(__float2bfloat16_rn(c[mf][nf][1] * sc));
            e1.x = __bfloat162float(__float2bfloat16_rn(c[mf][nf][2] * sc));
            e1.y = __bfloat162float(__float2bfloat16_rn(c[mf][nf][3] * sc));
            *reinterpret_cast<float2*>(out + (size_t)gm * N_DIM + gn) = e0;
            *reinterpret_cast<float2*>(out + (size_t)(gm + 8) * N_DIM + gn) = e1;
        }
    }
}

// ============================================================================
// Host launcher — exactly 4 launches (amax, scales, quant, gemm)
// ============================================================================
extern "C" void kernel_launch(void* const* d_in, const int* in_sizes, int n_in,
                              void* d_out, int out_size) {
    // x is the larger tensor, weight the smaller
    int ix = 0, iw = 1;
    if (n_in >= 2 && in_sizes[1] > in_sizes[0]) { ix = 1; iw = 0; }
    const float* x = (const float*)d_in[ix];
    const float* w = (const float*)d_in[iw];
    float* out = (float*)d_out;

    size_t nx = (size_t)in_sizes[ix];   // 16,777,216
    size_t nw = (size_t)in_sizes[iw];   //  4,194,304
    int M = (int)(nx / K_DIM);          // 8192

    void *xq = nullptr, *wq = nullptr;
    cudaGetSymbolAddress(&xq, g_x_fp8);
    cudaGetSymbolAddress(&wq, g_w_fp8);

    amax_both_kernel<<<XBLK + WBLK, 256>>>(x, nx / 4, w, nw / 4);
    scales_kernel<<<1, 256>>>();
    quant_both_kernel<<<QXB + QWB, 256>>>(x, (unsigned char*)xq, nx / 8,
                                          w, (unsigned char*)wq, nw / 8);

    cudaFuncSetAttribute(gemm_kernel, cudaFuncAttributeMaxDynamicSharedMemorySize, GEMM_SMEM);
    dim3 grid(M / BM, N_DIM / BN);
    gemm_kernel<<<grid, 256, GEMM_SMEM>>>((const uint8_t*)xq, (const uint8_t*)wq, out);
}

// round 8
// speedup vs baseline: 1.0847x; 1.0847x over previous
#include <cuda_runtime.h>
#include <cuda_bf16.h>
#include <cuda_fp8.h>
#include <cstdint>

// ============================================================================
// Problem constants — inputs and output are FLOAT32 buffers (bf16 values
// materialized as f32 by the harness; output compared as f32 of bf16 values)
// ============================================================================
static constexpr int K_DIM = 2048;
static constexpr int N_DIM = 2048;
static constexpr int M_MAX = 8192;

// amax partials layout
static constexpr int XBLK = 1536;   // partial-max blocks for x
static constexpr int WBLK = 768;    // partial-max blocks for w
static constexpr int QXB  = 2048;   // quant blocks for x
static constexpr int QWB  = 1024;   // quant blocks for w

// fp8 scratch + scalars (device globals — no allocation allowed)
__device__ __align__(128) unsigned char g_x_fp8[(size_t)M_MAX * K_DIM];  // 16 MB
__device__ __align__(128) unsigned char g_w_fp8[(size_t)N_DIM * K_DIM]; //  4 MB
__device__ float g_part[XBLK + WBLK];  // per-block partial maxes (pure writes)
__device__ float g_scale[2];           // per-tensor scale
__device__ float g_scale_comb;         // sx*sw for epilogue

__device__ __forceinline__ uint32_t smem_to_u32(const void* smem_ptr) {
    uint32_t addr;
    asm("{ .reg .u64 tmp; cvta.to.shared.u64 tmp, %1; cvt.u32.u64 %0, tmp; }"
        : "=r"(addr) : "l"(smem_ptr));
    return addr;
}

#define CP_ASYNC16(dst, src) \
    asm volatile("cp.async.cg.shared.global [%0], [%1], 16;" :: "r"(dst), "l"(src) : "memory")
#define CP_ASYNC_COMMIT() asm volatile("cp.async.commit_group;" ::: "memory")
#define CP_ASYNC_WAIT3()  asm volatile("cp.async.wait_group 3;" ::: "memory")

#define LDMATRIX_X4(r0, r1, r2, r3, addr) \
    asm volatile("ldmatrix.sync.aligned.m8n8.x4.shared.b16 {%0,%1,%2,%3}, [%4];" \
                 : "=r"(r0), "=r"(r1), "=r"(r2), "=r"(r3) : "r"(addr))

#define MMA_E4M3(c0, c1, c2, c3, a0, a1, a2, a3, b0, b1) \
    asm volatile("mma.sync.aligned.m16n8k32.row.col.f32.e4m3.e4m3.f32 " \
                 "{%0,%1,%2,%3}, {%4,%5,%6,%7}, {%8,%9}, {%0,%1,%2,%3};" \
                 : "+f"(c0), "+f"(c1), "+f"(c2), "+f"(c3) \
                 : "r"(a0), "r"(a1), "r"(a2), "r"(a3), "r"(b0), "r"(b1))

// ============================================================================
// Kernel 1: fused amax over both tensors -> per-block partials (no reset/atomic)
// ============================================================================
__device__ __forceinline__ float block_reduce_max(float m) {
    #pragma unroll
    for (int o = 16; o > 0; o >>= 1)
        m = fmaxf(m, __shfl_xor_sync(0xFFFFFFFFu, m, o));
    __shared__ float smax[8];
    int wid = threadIdx.x >> 5, lid = threadIdx.x & 31;
    if (lid == 0) smax[wid] = m;
    __syncthreads();
    if (wid == 0) {
        m = (lid < (int)(blockDim.x >> 5)) ? smax[lid] : 0.0f;
        #pragma unroll
        for (int o = 4; o > 0; o >>= 1)
            m = fmaxf(m, __shfl_xor_sync(0xFFFFFFFFu, m, o));
    }
    return m;
}

__global__ void amax_both_kernel(const float* __restrict__ x, size_t nx4,
                                 const float* __restrict__ w, size_t nw4) {
    bool is_x = (blockIdx.x < XBLK);
    const float4* p = reinterpret_cast<const float4*>(is_x ? x : w);
    size_t n4   = is_x ? nx4 : nw4;
    int    bid  = is_x ? blockIdx.x : (blockIdx.x - XBLK);
    int    nblk = is_x ? XBLK : WBLK;

    float m = 0.0f;
    size_t i = (size_t)bid * blockDim.x + threadIdx.x;
    size_t stride = (size_t)nblk * blockDim.x;
    for (; i < n4; i += stride) {
        float4 v = p[i];
        m = fmaxf(m, fmaxf(fmaxf(fabsf(v.x), fabsf(v.y)),
                           fmaxf(fabsf(v.z), fabsf(v.w))));
    }
    m = block_reduce_max(m);
    if (threadIdx.x == 0) g_part[blockIdx.x] = m;
}

// ============================================================================
// Kernel 2: reduce partials -> scales (pure function of g_part; no state)
// ============================================================================
__global__ void scales_kernel() {
    int tid = threadIdx.x;   // 256 threads
    float mx = 0.0f, mw = 0.0f;
    for (int i = tid; i < XBLK; i += 256) mx = fmaxf(mx, g_part[i]);
    for (int i = XBLK + tid; i < XBLK + WBLK; i += 256) mw = fmaxf(mw, g_part[i]);
    #pragma unroll
    for (int o = 16; o > 0; o >>= 1) {
        mx = fmaxf(mx, __shfl_xor_sync(0xFFFFFFFFu, mx, o));
        mw = fmaxf(mw, __shfl_xor_sync(0xFFFFFFFFu, mw, o));
    }
    __shared__ float sx8[8], sw8[8];
    int wid = tid >> 5, lid = tid & 31;
    if (lid == 0) { sx8[wid] = mx; sw8[wid] = mw; }
    __syncthreads();
    if (tid == 0) {
        float ax = 0.0f, aw = 0.0f;
        #pragma unroll
        for (int i = 0; i < 8; i++) {
            ax = fmaxf(ax, sx8[i]);
            aw = fmaxf(aw, sw8[i]);
        }
        float sxv = fmaxf(__fdiv_rn(ax, 448.0f), 1e-12f);
        float swv = fmaxf(__fdiv_rn(aw, 448.0f), 1e-12f);
        g_scale[0] = sxv;
        g_scale[1] = swv;
        g_scale_comb = sxv * swv;
    }
}

// ============================================================================
// Kernel 3: fused quantize f32 -> e4m3 for both tensors (RNE satfinite)
// ============================================================================
__global__ void quant_both_kernel(const float* __restrict__ x, unsigned char* __restrict__ xq, size_t nx8,
                                  const float* __restrict__ w, unsigned char* __restrict__ wq, size_t nw8) {
    bool is_x = (blockIdx.x < QXB);
    const float4* p = reinterpret_cast<const float4*>(is_x ? x : w);
    uint2* q  = reinterpret_cast<uint2*>(is_x ? xq : wq);
    size_t n8 = is_x ? nx8 : nw8;
    int bid   = is_x ? blockIdx.x : (blockIdx.x - QXB);
    int nblk  = is_x ? QXB : QWB;
    float s   = g_scale[is_x ? 0 : 1];

    size_t i = (size_t)bid * blockDim.x + threadIdx.x;
    size_t stride = (size_t)nblk * blockDim.x;
    for (; i < n8; i += stride) {
        float4 v0 = p[2 * i];
        float4 v1 = p[2 * i + 1];
        float2 f0 = make_float2(__fdiv_rn(v0.x, s), __fdiv_rn(v0.y, s));
        float2 f1 = make_float2(__fdiv_rn(v0.z, s), __fdiv_rn(v0.w, s));
        float2 f2 = make_float2(__fdiv_rn(v1.x, s), __fdiv_rn(v1.y, s));
        float2 f3 = make_float2(__fdiv_rn(v1.z, s), __fdiv_rn(v1.w, s));
        uint32_t b0 = __nv_cvt_float2_to_fp8x2(f0, __NV_SATFINITE, __NV_E4M3);
        uint32_t b1 = __nv_cvt_float2_to_fp8x2(f1, __NV_SATFINITE, __NV_E4M3);
        uint32_t b2 = __nv_cvt_float2_to_fp8x2(f2, __NV_SATFINITE, __NV_E4M3);
        uint32_t b3 = __nv_cvt_float2_to_fp8x2(f3, __NV_SATFINITE, __NV_E4M3);
        uint2 r;
        r.x = (b0 & 0xFFFFu) | (b1 << 16);
        r.y = (b2 & 0xFFFFu) | (b3 << 16);
        q[i] = r;
    }
}

// ============================================================================
// Kernel 4: FP8 GEMM via mma.sync.m16n8k32 e4m3
//   out[m,n] = f32(bf16(sc * sum_k A[m,k]*B[n,k]))
//   CTA 128x128, BK=64, 5-stage cp.async, ONE barrier per k-iter,
//   hoisted per-thread load addressing. 256 threads, 2 CTA/SM.
// ============================================================================
static constexpr int BM = 128, BN = 128, BK = 64;
static constexpr int STAGES = 5;
static constexpr int PITCH = 80;                    // bytes/row: conflict-free
static constexpr int TILE_A = BM * PITCH;           // 10240 bytes
static constexpr int STAGE_B = 2 * TILE_A;          // 20480 bytes per stage
static constexpr int GEMM_SMEM = STAGES * STAGE_B;  // 102400 bytes
static constexpr int KITERS = K_DIM / BK;           // 32

__global__ void __launch_bounds__(256, 2) gemm_kernel(
    const uint8_t* __restrict__ Aq, const uint8_t* __restrict__ Bq,
    float* __restrict__ out)
{
    extern __shared__ char smem[];
    uint32_t sbase = smem_to_u32(smem);
    int tid  = threadIdx.x;
    int lane = tid & 31;
    int wid  = tid >> 5;
    int warp_m = wid & 1;   // 0..1
    int warp_n = wid >> 1;  // 0..3
    int m0 = blockIdx.x * BM;
    int n0 = blockIdx.y * BN;

    // ---- hoisted per-thread cp.async addressing (loop-invariant) ----
    // 1024 chunks/stage: 512 A + 512 B; each thread owns 4 fixed chunks.
    const uint8_t* src[4];
    uint32_t       dof[4];   // smem offset within a stage
    #pragma unroll
    for (int p = 0; p < 4; p++) {
        int rid = (p * 256 + tid) & 511;
        int row = rid >> 2;
        int ch  = rid & 3;
        if (p < 2) {
            src[p] = Aq + (size_t)(m0 + row) * K_DIM + ch * 16;
            dof[p] = row * PITCH + ch * 16;
        } else {
            src[p] = Bq + (size_t)(n0 + row) * K_DIM + ch * 16;
            dof[p] = TILE_A + row * PITCH + ch * 16;
        }
    }

    float c[4][4][4];
    #pragma unroll
    for (int mf = 0; mf < 4; mf++)
        #pragma unroll
        for (int nf = 0; nf < 4; nf++)
            #pragma unroll
            for (int e = 0; e < 4; e++) c[mf][nf][e] = 0.0f;

    // prologue: fill 4 stages; src[p] advances by BK per stage
    #pragma unroll
    for (int ki = 0; ki < STAGES - 1; ki++) {
        uint32_t so = sbase + ki * STAGE_B;
        #pragma unroll
        for (int p = 0; p < 4; p++) {
            CP_ASYNC16(so + dof[p], src[p]);
            src[p] += BK;
        }
        CP_ASYNC_COMMIT();
    }

    // hoisted LDSM row bases
    int frow = lane & 15;
    int fch  = lane >> 4;
    uint32_t arow = (uint32_t)(warp_m * 64 + frow) * PITCH + fch * 16;
    uint32_t brow = TILE_A + (uint32_t)(warp_n * 32 + frow) * PITCH + fch * 16;

    uint32_t pf_off = (STAGES - 1) * STAGE_B;   // stage (ki+4)%5 byte offset
    uint32_t cs_off = 0;                        // stage ki%5 byte offset

    for (int ki = 0; ki < KITERS; ki++) {
        CP_ASYNC_WAIT3();
        __syncthreads();   // all warps done with stage (ki-1)%5; its refill is safe

        if (ki + STAGES - 1 < KITERS) {
            uint32_t so = sbase + pf_off;
            #pragma unroll
            for (int p = 0; p < 4; p++) {
                CP_ASYNC16(so + dof[p], src[p]);
                src[p] += BK;
            }
        }
        CP_ASYNC_COMMIT();
        pf_off += STAGE_B; if (pf_off == GEMM_SMEM) pf_off = 0;

        uint32_t sA = sbase + cs_off + arow;
        uint32_t sB = sbase + cs_off + brow;
        cs_off += STAGE_B; if (cs_off == GEMM_SMEM) cs_off = 0;

        #pragma unroll
        for (int ks = 0; ks < 2; ks++) {          // kk = ks*32
            uint32_t aAddr = sA + ks * 32;
            uint32_t bAddr = sB + ks * 32;

            uint32_t a[4][4];
            #pragma unroll
            for (int mf = 0; mf < 4; mf++)
                LDMATRIX_X4(a[mf][0], a[mf][1], a[mf][2], a[mf][3],
                            aAddr + mf * 16 * PITCH);

            uint32_t b[4][2];
            #pragma unroll
            for (int nfp = 0; nfp < 2; nfp++) {
                uint32_t r0, r1, r2, r3;
                LDMATRIX_X4(r0, r1, r2, r3, bAddr + nfp * 16 * PITCH);
                b[2 * nfp][0]     = r0;  b[2 * nfp][1]     = r2;  // n rows 0-7
                b[2 * nfp + 1][0] = r1;  b[2 * nfp + 1][1] = r3;  // n rows 8-15
            }

            #pragma unroll
            for (int mf = 0; mf < 4; mf++)
                #pragma unroll
                for (int nf = 0; nf < 4; nf++)
                    MMA_E4M3(c[mf][nf][0], c[mf][nf][1], c[mf][nf][2], c[mf][nf][3],
                             a[mf][0], a[mf][1], a[mf][2], a[mf][3],
                             b[nf][0], b[nf][1]);
        }
        // no trailing barrier: next iteration's leading barrier guards reuse
    }

    // epilogue: scale, round to bf16 (reference casts to bf16), store as f32
    float sc = g_scale_comb;
    int r  = lane >> 2;
    int cq = (lane & 3) * 2;
    #pragma unroll
    for (int mf = 0; mf < 4; mf++) {
        #pragma unroll
        for (int nf = 0; nf < 4; nf++) {
            int gm = m0 + warp_m * 64 + mf * 16 + r;
            int gn = n0 + warp_n * 32 + nf * 8 + cq;
            float2 e0, e1;
            e0.x = __bfloat162float(__float2bfloat16_rn(c[mf][nf][0] * sc));
            e0.y = __bfloat162float(__float2bfloat16_rn(c[mf][nf][1] * sc));
            e1.x = __bfloat162float(__float2bfloat16_rn(c[mf][nf][2] * sc));
            e1.y = __bfloat162float(__float2bfloat16_rn(c[mf][nf][3] * sc));
            *reinterpret_cast<float2*>(out + (size_t)gm * N_DIM + gn) = e0;
            *reinterpret_cast<float2*>(out + (size_t)(gm + 8) * N_DIM + gn) = e1;
        }
    }
}

// ============================================================================
// Host launcher — exactly 4 launches (amax, scales, quant, gemm)
// ============================================================================
extern "C" void kernel_launch(void* const* d_in, const int* in_sizes, int n_in,
                              void* d_out, int out_size) {
    // x is the larger tensor, weight the smaller
    int ix = 0, iw = 1;
    if (n_in >= 2 && in_sizes[1] > in_sizes[0]) { ix = 1; iw = 0; }
    const float* x = (const float*)d_in[ix];
    const float* w = (const float*)d_in[iw];
    float* out = (float*)d_out;

    size_t nx = (size_t)in_sizes[ix];   // 16,777,216
    size_t nw = (size_t)in_sizes[iw];   //  4,194,304
    int M = (int)(nx / K_DIM);          // 8192

    void *xq = nullptr, *wq = nullptr;
    cudaGetSymbolAddress(&xq, g_x_fp8);
    cudaGetSymbolAddress(&wq, g_w_fp8);

    amax_both_kernel<<<XBLK + WBLK, 256>>>(x, nx / 4, w, nw / 4);
    scales_kernel<<<1, 256>>>();
    quant_both_kernel<<<QXB + QWB, 256>>>(x, (unsigned char*)xq, nx / 8,
                                          w, (unsigned char*)wq, nw / 8);

    cudaFuncSetAttribute(gemm_kernel, cudaFuncAttributeMaxDynamicSharedMemorySize, GEMM_SMEM);
    dim3 grid(M / BM, N_DIM / BN);
    gemm_kernel<<<grid, 256, GEMM_SMEM>>>((const uint8_t*)xq, (const uint8_t*)wq, out);
}

// round 9
// speedup vs baseline: 1.0933x; 1.0079x over previous
#include <cuda_runtime.h>
#include <cuda_bf16.h>
#include <cuda_fp8.h>
#include <cstdint>

// ============================================================================
// Problem constants — inputs and output are FLOAT32 buffers (bf16 values
// materialized as f32 by the harness; output compared as f32 of bf16 values)
// ============================================================================
static constexpr int K_DIM = 2048;
static constexpr int N_DIM = 2048;
static constexpr int M_MAX = 8192;

// amax partials layout
static constexpr int XBLK = 1536;
static constexpr int WBLK = 768;
static constexpr int QXB  = 2048;
static constexpr int QWB  = 1024;

// fp8 scratch + scalars (device globals — no allocation allowed)
__device__ __align__(128) unsigned char g_x_fp8[(size_t)M_MAX * K_DIM];  // 16 MB
__device__ __align__(128) unsigned char g_w_fp8[(size_t)N_DIM * K_DIM]; //  4 MB
__device__ float g_part[XBLK + WBLK];
__device__ float g_scale[2];
__device__ float g_scale_comb;

__device__ __forceinline__ uint32_t smem_to_u32(const void* smem_ptr) {
    uint32_t addr;
    asm("{ .reg .u64 tmp; cvta.to.shared.u64 tmp, %1; cvt.u32.u64 %0, tmp; }"
        : "=r"(addr) : "l"(smem_ptr));
    return addr;
}

#define CP_ASYNC16_OFF(dst, dimm, src, simm) \
    asm volatile("cp.async.cg.shared.global [%0+%1], [%2+%3], 16;" \
                 :: "r"(dst), "n"(dimm), "l"(src), "n"(simm) : "memory")
#define CP_ASYNC_COMMIT() asm volatile("cp.async.commit_group;" ::: "memory")
#define CP_ASYNC_WAIT1()  asm volatile("cp.async.wait_group 1;" ::: "memory")

#define LDMATRIX_X4_OFF(r0, r1, r2, r3, addr, imm) \
    asm volatile("ldmatrix.sync.aligned.m8n8.x4.shared.b16 {%0,%1,%2,%3}, [%4+%5];" \
                 : "=r"(r0), "=r"(r1), "=r"(r2), "=r"(r3) : "r"(addr), "n"(imm))

#define MMA_E4M3(c0, c1, c2, c3, a0, a1, a2, a3, b0, b1) \
    asm volatile("mma.sync.aligned.m16n8k32.row.col.f32.e4m3.e4m3.f32 " \
                 "{%0,%1,%2,%3}, {%4,%5,%6,%7}, {%8,%9}, {%0,%1,%2,%3};" \
                 : "+f"(c0), "+f"(c1), "+f"(c2), "+f"(c3) \
                 : "r"(a0), "r"(a1), "r"(a2), "r"(a3), "r"(b0), "r"(b1))

// ============================================================================
// Kernel 1: fused amax over both tensors -> per-block partials
// ============================================================================
__device__ __forceinline__ float block_reduce_max(float m) {
    #pragma unroll
    for (int o = 16; o > 0; o >>= 1)
        m = fmaxf(m, __shfl_xor_sync(0xFFFFFFFFu, m, o));
    __shared__ float smax[8];
    int wid = threadIdx.x >> 5, lid = threadIdx.x & 31;
    if (lid == 0) smax[wid] = m;
    __syncthreads();
    if (wid == 0) {
        m = (lid < (int)(blockDim.x >> 5)) ? smax[lid] : 0.0f;
        #pragma unroll
        for (int o = 4; o > 0; o >>= 1)
            m = fmaxf(m, __shfl_xor_sync(0xFFFFFFFFu, m, o));
    }
    return m;
}

__global__ void amax_both_kernel(const float* __restrict__ x, size_t nx4,
                                 const float* __restrict__ w, size_t nw4) {
    bool is_x = (blockIdx.x < XBLK);
    const float4* p = reinterpret_cast<const float4*>(is_x ? x : w);
    size_t n4   = is_x ? nx4 : nw4;
    int    bid  = is_x ? blockIdx.x : (blockIdx.x - XBLK);
    int    nblk = is_x ? XBLK : WBLK;

    float m = 0.0f;
    size_t i = (size_t)bid * blockDim.x + threadIdx.x;
    size_t stride = (size_t)nblk * blockDim.x;
    for (; i < n4; i += stride) {
        float4 v = p[i];
        m = fmaxf(m, fmaxf(fmaxf(fabsf(v.x), fabsf(v.y)),
                           fmaxf(fabsf(v.z), fabsf(v.w))));
    }
    m = block_reduce_max(m);
    if (threadIdx.x == 0) g_part[blockIdx.x] = m;
}

// ============================================================================
// Kernel 2: reduce partials -> scales
// ============================================================================
__global__ void scales_kernel() {
    int tid = threadIdx.x;   // 256 threads
    float mx = 0.0f, mw = 0.0f;
    for (int i = tid; i < XBLK; i += 256) mx = fmaxf(mx, g_part[i]);
    for (int i = XBLK + tid; i < XBLK + WBLK; i += 256) mw = fmaxf(mw, g_part[i]);
    #pragma unroll
    for (int o = 16; o > 0; o >>= 1) {
        mx = fmaxf(mx, __shfl_xor_sync(0xFFFFFFFFu, mx, o));
        mw = fmaxf(mw, __shfl_xor_sync(0xFFFFFFFFu, mw, o));
    }
    __shared__ float sx8[8], sw8[8];
    int wid = tid >> 5, lid = tid & 31;
    if (lid == 0) { sx8[wid] = mx; sw8[wid] = mw; }
    __syncthreads();
    if (tid == 0) {
        float ax = 0.0f, aw = 0.0f;
        #pragma unroll
        for (int i = 0; i < 8; i++) {
            ax = fmaxf(ax, sx8[i]);
            aw = fmaxf(aw, sw8[i]);
        }
        float sxv = fmaxf(__fdiv_rn(ax, 448.0f), 1e-12f);
        float swv = fmaxf(__fdiv_rn(aw, 448.0f), 1e-12f);
        g_scale[0] = sxv;
        g_scale[1] = swv;
        g_scale_comb = sxv * swv;
    }
}

// ============================================================================
// Kernel 3: fused quantize f32 -> e4m3 for both tensors (RNE satfinite)
// ============================================================================
__global__ void quant_both_kernel(const float* __restrict__ x, unsigned char* __restrict__ xq, size_t nx8,
                                  const float* __restrict__ w, unsigned char* __restrict__ wq, size_t nw8) {
    bool is_x = (blockIdx.x < QXB);
    const float4* p = reinterpret_cast<const float4*>(is_x ? x : w);
    uint2* q  = reinterpret_cast<uint2*>(is_x ? xq : wq);
    size_t n8 = is_x ? nx8 : nw8;
    int bid   = is_x ? blockIdx.x : (blockIdx.x - QXB);
    int nblk  = is_x ? QXB : QWB;
    float s   = g_scale[is_x ? 0 : 1];

    size_t i = (size_t)bid * blockDim.x + threadIdx.x;
    size_t stride = (size_t)nblk * blockDim.x;
    for (; i < n8; i += stride) {
        float4 v0 = p[2 * i];
        float4 v1 = p[2 * i + 1];
        float2 f0 = make_float2(__fdiv_rn(v0.x, s), __fdiv_rn(v0.y, s));
        float2 f1 = make_float2(__fdiv_rn(v0.z, s), __fdiv_rn(v0.w, s));
        float2 f2 = make_float2(__fdiv_rn(v1.x, s), __fdiv_rn(v1.y, s));
        float2 f3 = make_float2(__fdiv_rn(v1.z, s), __fdiv_rn(v1.w, s));
        uint32_t b0 = __nv_cvt_float2_to_fp8x2(f0, __NV_SATFINITE, __NV_E4M3);
        uint32_t b1 = __nv_cvt_float2_to_fp8x2(f1, __NV_SATFINITE, __NV_E4M3);
        uint32_t b2 = __nv_cvt_float2_to_fp8x2(f2, __NV_SATFINITE, __NV_E4M3);
        uint32_t b3 = __nv_cvt_float2_to_fp8x2(f3, __NV_SATFINITE, __NV_E4M3);
        uint2 r;
        r.x = (b0 & 0xFFFFu) | (b1 << 16);
        r.y = (b2 & 0xFFFFu) | (b3 << 16);
        q[i] = r;
    }
}

// ============================================================================
// Kernel 4: FP8 GEMM via mma.sync.m16n8k32 e4m3
//   CTA 128x128, BK=128 bytes, 3-stage cp.async, one barrier per k-iter,
//   ALL smem/gmem offsets as instruction immediates. 256 thr, 2 CTA/SM.
// ============================================================================
static constexpr int BM = 128, BN = 128, BK = 128;
static constexpr int STAGES = 3;
static constexpr int PITCH = 144;                   // 128 data + 16 pad: conflict-free
static constexpr int TILE_A = BM * PITCH;           // 18432 bytes
static constexpr int STAGE_B = 2 * TILE_A;          // 36864 bytes per stage
static constexpr int GEMM_SMEM = STAGES * STAGE_B;  // 110592 bytes
static constexpr int KITERS = K_DIM / BK;           // 16
static constexpr int MF_STEP = 16 * PITCH;          // 2304

// one k32 step: 4 A-LDSM + 2 B-LDSM + 16 MMA, all offsets immediate
template <int KS>
__device__ __forceinline__ void kstep(uint32_t aB, uint32_t bB, float (&c)[4][4][4]) {
    uint32_t a[4][4];
    LDMATRIX_X4_OFF(a[0][0], a[0][1], a[0][2], a[0][3], aB, 0 * MF_STEP + KS * 32);
    LDMATRIX_X4_OFF(a[1][0], a[1][1], a[1][2], a[1][3], aB, 1 * MF_STEP + KS * 32);
    LDMATRIX_X4_OFF(a[2][0], a[2][1], a[2][2], a[2][3], aB, 2 * MF_STEP + KS * 32);
    LDMATRIX_X4_OFF(a[3][0], a[3][1], a[3][2], a[3][3], aB, 3 * MF_STEP + KS * 32);

    uint32_t b[4][2];
    {
        uint32_t r0, r1, r2, r3;
        LDMATRIX_X4_OFF(r0, r1, r2, r3, bB, 0 * MF_STEP + KS * 32);
        b[0][0] = r0; b[0][1] = r2;
        b[1][0] = r1; b[1][1] = r3;
        LDMATRIX_X4_OFF(r0, r1, r2, r3, bB, 1 * MF_STEP + KS * 32);
        b[2][0] = r0; b[2][1] = r2;
        b[3][0] = r1; b[3][1] = r3;
    }

    #pragma unroll
    for (int mf = 0; mf < 4; mf++)
        #pragma unroll
        for (int nf = 0; nf < 4; nf++)
            MMA_E4M3(c[mf][nf][0], c[mf][nf][1], c[mf][nf][2], c[mf][nf][3],
                     a[mf][0], a[mf][1], a[mf][2], a[mf][3],
                     b[nf][0], b[nf][1]);
}

// issue the 8 cp.async chunks for one stage; src offsets / dst offsets immediate
__device__ __forceinline__ void load_stage(uint32_t d0, const uint8_t* sA, const uint8_t* sB) {
    CP_ASYNC16_OFF(d0, 0 * 4608,          sA, 0 * 32 * K_DIM);
    CP_ASYNC16_OFF(d0, 1 * 4608,          sA, 1 * 32 * K_DIM);
    CP_ASYNC16_OFF(d0, 2 * 4608,          sA, 2 * 32 * K_DIM);
    CP_ASYNC16_OFF(d0, 3 * 4608,          sA, 3 * 32 * K_DIM);
    CP_ASYNC16_OFF(d0, TILE_A + 0 * 4608, sB, 0 * 32 * K_DIM);
    CP_ASYNC16_OFF(d0, TILE_A + 1 * 4608, sB, 1 * 32 * K_DIM);
    CP_ASYNC16_OFF(d0, TILE_A + 2 * 4608, sB, 2 * 32 * K_DIM);
    CP_ASYNC16_OFF(d0, TILE_A + 3 * 4608, sB, 3 * 32 * K_DIM);
}

__global__ void __launch_bounds__(256, 2) gemm_kernel(
    const uint8_t* __restrict__ Aq, const uint8_t* __restrict__ Bq,
    float* __restrict__ out)
{
    extern __shared__ char smem[];
    uint32_t sbase = smem_to_u32(smem);
    int tid  = threadIdx.x;
    int lane = tid & 31;
    int wid  = tid >> 5;
    int warp_m = wid & 1;
    int warp_n = wid >> 1;
    int m0 = blockIdx.x * BM;
    int n0 = blockIdx.y * BN;

    // per-thread load bases: thread covers row (tid>>3)+32p, chunk (tid&7)
    int lrow = tid >> 3;
    int lch  = (tid & 7) * 16;
    const uint8_t* srcA = Aq + (size_t)(m0 + lrow) * K_DIM + lch;
    const uint8_t* srcB = Bq + (size_t)(n0 + lrow) * K_DIM + lch;
    uint32_t dof0 = (uint32_t)lrow * PITCH + lch;   // stage-relative dst

    float c[4][4][4];
    #pragma unroll
    for (int mf = 0; mf < 4; mf++)
        #pragma unroll
        for (int nf = 0; nf < 4; nf++)
            #pragma unroll
            for (int e = 0; e < 4; e++) c[mf][nf][e] = 0.0f;

    // prologue: stages 0,1
    load_stage(sbase + 0 * STAGE_B + dof0, srcA, srcB); srcA += BK; srcB += BK;
    CP_ASYNC_COMMIT();
    load_stage(sbase + 1 * STAGE_B + dof0, srcA, srcB); srcA += BK; srcB += BK;
    CP_ASYNC_COMMIT();

    // hoisted LDSM row bases
    int frow = lane & 15;
    int fch  = lane >> 4;
    uint32_t arow = (uint32_t)(warp_m * 64 + frow) * PITCH + fch * 16;
    uint32_t brow = TILE_A + (uint32_t)(warp_n * 32 + frow) * PITCH + fch * 16;

    uint32_t pf_off = 2 * STAGE_B;   // stage (ki+2)%3 byte offset
    uint32_t cs_off = 0;             // stage ki%3 byte offset

    for (int ki = 0; ki < KITERS; ki++) {
        CP_ASYNC_WAIT1();
        __syncthreads();   // stage (ki-1)%3 fully consumed by all warps

        if (ki + 2 < KITERS) {
            load_stage(sbase + pf_off + dof0, srcA, srcB);
            srcA += BK; srcB += BK;
        }
        CP_ASYNC_COMMIT();
        pf_off += STAGE_B; if (pf_off == GEMM_SMEM) pf_off = 0;

        uint32_t aB = sbase + cs_off + arow;
        uint32_t bB = sbase + cs_off + brow;
        cs_off += STAGE_B; if (cs_off == GEMM_SMEM) cs_off = 0;

        kstep<0>(aB, bB, c);
        kstep<1>(aB, bB, c);
        kstep<2>(aB, bB, c);
        kstep<3>(aB, bB, c);
    }

    // epilogue: scale, round to bf16 (reference casts to bf16), store as f32
    float sc = g_scale_comb;
    int r  = lane >> 2;
    int cq = (lane & 3) * 2;
    #pragma unroll
    for (int mf = 0; mf < 4; mf++) {
        #pragma unroll
        for (int nf = 0; nf < 4; nf++) {
            int gm = m0 + warp_m * 64 + mf * 16 + r;
            int gn = n0 + warp_n * 32 + nf * 8 + cq;
            float2 e0, e1;
            e0.x = __bfloat162float(__float2bfloat16_rn(c[mf][nf][0] * sc));
            e0.y = __bfloat162float(__float2bfloat16_rn(c[mf][nf][1] * sc));
            e1.x = __bfloat162float(__float2bfloat16_rn(c[mf][nf][2] * sc));
            e1.y = __bfloat162float(__float2bfloat16_rn(c[mf][nf][3] * sc));
            *reinterpret_cast<float2*>(out + (size_t)gm * N_DIM + gn) = e0;
            *reinterpret_cast<float2*>(out + (size_t)(gm + 8) * N_DIM + gn) = e1;
        }
    }
}

// ============================================================================
// Host launcher — exactly 4 launches (amax, scales, quant, gemm)
// ============================================================================
extern "C" void kernel_launch(void* const* d_in, const int* in_sizes, int n_in,
                              void* d_out, int out_size) {
    int ix = 0, iw = 1;
    if (n_in >= 2 && in_sizes[1] > in_sizes[0]) { ix = 1; iw = 0; }
    const float* x = (const float*)d_in[ix];
    const float* w = (const float*)d_in[iw];
    float* out = (float*)d_out;

    size_t nx = (size_t)in_sizes[ix];   // 16,777,216
    size_t nw = (size_t)in_sizes[iw];   //  4,194,304
    int M = (int)(nx / K_DIM);          // 8192

    void *xq = nullptr, *wq = nullptr;
    cudaGetSymbolAddress(&xq, g_x_fp8);
    cudaGetSymbolAddress(&wq, g_w_fp8);

    amax_both_kernel<<<XBLK + WBLK, 256>>>(x, nx / 4, w, nw / 4);
    scales_kernel<<<1, 256>>>();
    quant_both_kernel<<<QXB + QWB, 256>>>(x, (unsigned char*)xq, nx / 8,
                                          w, (unsigned char*)wq, nw / 8);

    cudaFuncSetAttribute(gemm_kernel, cudaFuncAttributeMaxDynamicSharedMemorySize, GEMM_SMEM);
    dim3 grid(M / BM, N_DIM / BN);
    gemm_kernel<<<grid, 256, GEMM_SMEM>>>((const uint8_t*)xq, (const uint8_t*)wq, out);
}